// round 16
// baseline (speedup 1.0000x reference)
#include <cuda_runtime.h>
#include <cuda_bf16.h>
#include <cuda_fp16.h>
#include <cstdint>

#define CC 128
#define HH 256
#define LL 4
#define NMAX 50176
#define EMAX 602112

// ---------------- scratch (device globals; no allocation allowed) ------------
__device__ float  g_x [NMAX * CC];
__device__ float  g_o [NMAX * CC];
__device__ float  g_h1[NMAX * HH];
__device__ __half g_yh[NMAX * CC];   // fp16 image of relu(GN(x)) (gather operand)
__device__ int    g_rowptr[NMAX + 1];
__device__ int    g_cursor[NMAX];
__device__ int    g_col[EMAX];
__device__ int    g_part[64];
__device__ float  g_gnsum[CC];
__device__ float  g_gnsq [CC];
__device__ double g_lnsum;
__device__ double g_lnsq;
// bf16 hi/lo weight images, [n][k] row-major, per layer (32768 elems each)
__device__ __align__(16) __nv_bfloat16 g_B1h[LL * 32768];
__device__ __align__(16) __nv_bfloat16 g_B1l[LL * 32768];
__device__ __align__(16) __nv_bfloat16 g_B2h[LL * 32768];
__device__ __align__(16) __nv_bfloat16 g_B2l[LL * 32768];

// ---------------- mma.sync helpers (legal on plain sm_100) -------------------
__device__ __forceinline__ uint32_t smem_to_u32(const void* p) {
    uint32_t a;
    asm("{ .reg .u64 t; cvta.to.shared.u64 t, %1; cvt.u32.u64 %0, t; }" : "=r"(a) : "l"(p));
    return a;
}
__device__ __forceinline__ void ldsm4(uint32_t* r, uint32_t a) {
    asm volatile("ldmatrix.sync.aligned.m8n8.x4.shared.b16 {%0,%1,%2,%3}, [%4];"
                 : "=r"(r[0]), "=r"(r[1]), "=r"(r[2]), "=r"(r[3]) : "r"(a));
}
__device__ __forceinline__ void ldsm2(uint32_t* r, uint32_t a) {
    asm volatile("ldmatrix.sync.aligned.m8n8.x2.shared.b16 {%0,%1}, [%2];"
                 : "=r"(r[0]), "=r"(r[1]) : "r"(a));
}
__device__ __forceinline__ void mma_bf16(float* c, const uint32_t* a, const uint32_t* b) {
    asm volatile(
        "mma.sync.aligned.m16n8k16.row.col.f32.bf16.bf16.f32 "
        "{%0,%1,%2,%3}, {%4,%5,%6,%7}, {%8,%9}, {%0,%1,%2,%3};"
        : "+f"(c[0]), "+f"(c[1]), "+f"(c[2]), "+f"(c[3])
        : "r"(a[0]), "r"(a[1]), "r"(a[2]), "r"(a[3]), "r"(b[0]), "r"(b[1]));
}
__device__ __forceinline__ void bsplit(float v, __nv_bfloat16& h, __nv_bfloat16& l) {
    h = __float2bfloat16(v);
    l = __float2bfloat16(v - __bfloat162float(h));
}
__device__ __forceinline__ uint32_t pk(__nv_bfloat16 a, __nv_bfloat16 b) {
    __nv_bfloat162 t; t.x = a; t.y = b;
    return *reinterpret_cast<uint32_t*>(&t);
}

// smem tile pitch: 40 bf16 (80 B) -> ldmatrix rows hit distinct bank groups
#define PITCH 40

// ---------------- init: cursor zero + stats zero + out = lin_b ---------------
__global__ void k_init(int n, float* __restrict__ out, const float* __restrict__ linb)
{
    int i = blockIdx.x * blockDim.x + threadIdx.x;
    if (i < n) {
        g_cursor[i] = 0;
        out[i] = __ldg(linb);
    }
    if (blockIdx.x == 0) {
        if (threadIdx.x < 128) { g_gnsum[threadIdx.x] = 0.f; g_gnsq[threadIdx.x] = 0.f; }
        if (threadIdx.x == 128) g_lnsum = 0.0;
        if (threadIdx.x == 129) g_lnsq  = 0.0;
    }
}

// ---- mega setup: copyin+gn-stats (blocks 0..511) | wconv (512..1535) | count (1536..2047)
__global__ void k_setup(const float* __restrict__ x, int n,
                        const float* __restrict__ W1, const float* __restrict__ W2,
                        const int* __restrict__ dst, int E)
{
    int b = blockIdx.x;
    int tid = threadIdx.x;
    if (b < 512) {
        int c = tid & 127, sub = tid >> 7;
        float s = 0.f, q = 0.f;
        for (int row = b * 2 + sub; row < n; row += 1024) {
            float v = x[(size_t)row * CC + c];
            g_x[(size_t)row * CC + c] = v;
            s += v;
            q += v * v;
        }
        atomicAdd(&g_gnsum[c], s);
        atomicAdd(&g_gnsq[c],  q);
    } else if (b < 1536) {
        int i = (b - 512) * 256 + tid;
        int l = i >> 16;
        int r = i & 65535;
        __nv_bfloat16 h, lo;
        if (r < 32768) {                 // B1[n][k] = W1[l][k][n]
            int nn = r >> 7, k = r & 127;
            float v = W1[((size_t)l * CC + k) * HH + nn];
            bsplit(v, h, lo);
            g_B1h[l * 32768 + nn * 128 + k] = h;
            g_B1l[l * 32768 + nn * 128 + k] = lo;
        } else {                          // B2[n][k] = W2[l][k][n]
            r -= 32768;
            int nn = r >> 8, k = r & 255;
            float v = W2[((size_t)l * HH + k) * CC + nn];
            bsplit(v, h, lo);
            g_B2h[l * 32768 + nn * 256 + k] = h;
            g_B2l[l * 32768 + nn * 256 + k] = lo;
        }
    } else {
        int i = (b - 1536) * 256 + tid;
        for (; i < E; i += 512 * 256) atomicAdd(&g_cursor[dst[i]], 1);
    }
}

// ---------------- CSR scan + fill ---------------------------------------------
__global__ void k_scan1(int n)
{
    __shared__ int sh[1024];
    int i = blockIdx.x * 1024 + threadIdx.x;
    int v = (i < n) ? g_cursor[i] : 0;
    sh[threadIdx.x] = v;
    __syncthreads();
    for (int off = 1; off < 1024; off <<= 1) {
        int tv = (threadIdx.x >= off) ? sh[threadIdx.x - off] : 0;
        __syncthreads();
        sh[threadIdx.x] += tv;
        __syncthreads();
    }
    if (i < n) g_rowptr[i] = sh[threadIdx.x] - v;
    if (threadIdx.x == 1023) g_part[blockIdx.x] = sh[1023];
}

__global__ void k_scan2(int nb, int n, int E)
{
    int tid = threadIdx.x;  // 64 threads
    int v = (tid < nb) ? g_part[tid] : 0;
    int x = v;
    for (int off = 1; off < 32; off <<= 1) {
        int y = __shfl_up_sync(0xFFFFFFFFu, x, off);
        if ((tid & 31) >= off) x += y;
    }
    __shared__ int c0;
    if (tid == 31) c0 = x;
    __syncthreads();
    if (tid >= 32) x += c0;
    if (tid < nb) g_part[tid] = x - v;
    if (tid == 0) g_rowptr[n] = E;
}

__global__ void k_scan3(int n)
{
    int i = blockIdx.x * blockDim.x + threadIdx.x;
    if (i < n) {
        int val = g_rowptr[i] + g_part[i >> 10];
        g_rowptr[i] = val;
        g_cursor[i] = val;
    }
}

__global__ void k_fill(const int* __restrict__ src, const int* __restrict__ dst, int E)
{
    int i = blockIdx.x * blockDim.x + threadIdx.x;
    int stride = gridDim.x * blockDim.x;
    for (; i < E; i += stride) {
        int p = atomicAdd(&g_cursor[dst[i]], 1);
        g_col[p] = src[i];
    }
}

// ---- per-layer: y = relu(GN(x)) materialized as fp16 (gather operand) -------
__global__ void k_gn(int n, const float* __restrict__ gnw,
                     const float* __restrict__ gnb, const float* __restrict__ gna)
{
    int c = threadIdx.x;   // 128 threads, thread = channel
    float invn = 1.f / (float)n;
    float mean = g_gnsum[c] * invn;
    float a    = gna[c];
    float var  = g_gnsq[c] * invn - (2.f * a - a * a) * mean * mean;
    float winv = gnw[c] * rsqrtf(var + 1e-5f);
    float am   = a * mean;
    float b    = gnb[c];
    for (int row = blockIdx.x; row < n; row += gridDim.x) {
        float v = g_x[(size_t)row * CC + c];
        g_yh[(size_t)row * CC + c] = __float2half(fmaxf(winv * (v - am) + b, 0.f));
    }
}

// ---- GENConv softmax aggregation: fp16 gather, exact fp32 self term ---------
__global__ void k_edge(int n, const float* __restrict__ gnw,
                       const float* __restrict__ gnb, const float* __restrict__ gna,
                       const float* __restrict__ t_ptr)
{
    if (blockIdx.x == 0) {
        if (threadIdx.x == 0) g_lnsum = 0.0;
        if (threadIdx.x == 1) g_lnsq  = 0.0;
    }
    int warp = (blockIdx.x * blockDim.x + threadIdx.x) >> 5;
    if (warp >= n) return;
    int lane = threadIdx.x & 31;
    int co = lane * 4;
    float t = __ldg(t_ptr);

    int beg = g_rowptr[warp], end = g_rowptr[warp + 1];

    float4 s1a = make_float4(0.f, 0.f, 0.f, 0.f);
    float4 s2a = make_float4(0.f, 0.f, 0.f, 0.f);
    float4 s1b = make_float4(0.f, 0.f, 0.f, 0.f);
    float4 s2b = make_float4(0.f, 0.f, 0.f, 0.f);

#define EAT(u, S1, S2) { \
    float2 f0 = __half22float2(*reinterpret_cast<const __half2*>(&(u).x)); \
    float2 f1 = __half22float2(*reinterpret_cast<const __half2*>(&(u).y)); \
    float rx = f0.x + 1e-7f, ry = f0.y + 1e-7f; \
    float rz = f1.x + 1e-7f, rw = f1.y + 1e-7f; \
    float ex = __expf(t * rx), ey = __expf(t * ry); \
    float ez = __expf(t * rz), ew = __expf(t * rw); \
    S1.x += ex; S1.y += ey; S1.z += ez; S1.w += ew; \
    S2.x += rx * ex; S2.y += ry * ey; S2.z += rz * ez; S2.w += rw * ew; }

    int e = beg;
    for (; e + 4 <= end; e += 4) {
        int i0 = g_col[e],     i1 = g_col[e + 1];
        int i2 = g_col[e + 2], i3 = g_col[e + 3];
        uint2 u0 = __ldg((const uint2*)(g_yh + (size_t)i0 * CC + co));
        uint2 u1 = __ldg((const uint2*)(g_yh + (size_t)i1 * CC + co));
        uint2 u2 = __ldg((const uint2*)(g_yh + (size_t)i2 * CC + co));
        uint2 u3 = __ldg((const uint2*)(g_yh + (size_t)i3 * CC + co));
        EAT(u0, s1a, s2a)
        EAT(u1, s1b, s2b)
        EAT(u2, s1a, s2a)
        EAT(u3, s1b, s2b)
    }
    for (; e < end; e++) {
        int i0 = g_col[e];
        uint2 u0 = __ldg((const uint2*)(g_yh + (size_t)i0 * CC + co));
        EAT(u0, s1a, s2a)
    }
    s1a.x += s1b.x; s1a.y += s1b.y; s1a.z += s1b.z; s1a.w += s1b.w;
    s2a.x += s2b.x; s2a.y += s2b.y; s2a.z += s2b.z; s2a.w += s2b.w;

    // exact self term: GN+ReLU on own fp32 row
    float invn = 1.f / (float)n;
    float4 s4 = *(const float4*)(g_gnsum + co);
    float4 q4 = *(const float4*)(g_gnsq  + co);
    float4 a4 = __ldg((const float4*)(gna + co));
    float4 w4 = __ldg((const float4*)(gnw + co));
    float4 b4 = __ldg((const float4*)(gnb + co));
    float mX = s4.x * invn, mY = s4.y * invn, mZ = s4.z * invn, mW = s4.w * invn;
    float wvX = w4.x * rsqrtf(q4.x * invn - (2.f * a4.x - a4.x * a4.x) * mX * mX + 1e-5f);
    float wvY = w4.y * rsqrtf(q4.y * invn - (2.f * a4.y - a4.y * a4.y) * mY * mY + 1e-5f);
    float wvZ = w4.z * rsqrtf(q4.z * invn - (2.f * a4.z - a4.z * a4.z) * mZ * mZ + 1e-5f);
    float wvW = w4.w * rsqrtf(q4.w * invn - (2.f * a4.w - a4.w * a4.w) * mW * mW + 1e-5f);
    float4 hx = *(const float4*)(g_x + (size_t)warp * CC + co);
    float hX = fmaxf(wvX * (hx.x - a4.x * mX) + b4.x, 0.f);
    float hY = fmaxf(wvY * (hx.y - a4.y * mY) + b4.y, 0.f);
    float hZ = fmaxf(wvZ * (hx.z - a4.z * mZ) + b4.z, 0.f);
    float hW = fmaxf(wvW * (hx.w - a4.w * mW) + b4.w, 0.f);
    float4 o;
    o.x = s2a.x / (s1a.x + 1e-16f) + hX;
    o.y = s2a.y / (s1a.y + 1e-16f) + hY;
    o.z = s2a.z / (s1a.z + 1e-16f) + hZ;
    o.w = s2a.w / (s1a.w + 1e-16f) + hW;
    *(float4*)(g_o + (size_t)warp * CC + co) = o;
}

// ---------------- GEMM1 (mma.sync bf16-split): h1 = o @ W1 + b1 + LN stats ---
__global__ __launch_bounds__(256)
void k_gemm1_mma(int M, int layer, const float* __restrict__ b1l)
{
    __shared__ __align__(16) __nv_bfloat16 sm[4 * 128 * PITCH];
    __shared__ float rs[8], rq[8];
    const int AHI = 0, ALO = 128 * PITCH, BHI = 2 * 128 * PITCH, BLO = 3 * 128 * PITCH;

    int tid = threadIdx.x, lane = tid & 31, wid = tid >> 5;
    if (blockIdx.x == 0 && blockIdx.y == 0 && tid < 128) {
        g_gnsum[tid] = 0.f;
        g_gnsq[tid]  = 0.f;
    }
    int wm = wid & 1, wn = wid >> 1;
    int rowBase = blockIdx.x * 128;
    int colBase = blockIdx.y * 128;
    const __nv_bfloat16* B1h = g_B1h + (size_t)layer * 32768;
    const __nv_bfloat16* B1l = g_B1l + (size_t)layer * 32768;
    uint32_t sbase = smem_to_u32(sm);

    float c[4][4][4];
#pragma unroll
    for (int mt = 0; mt < 4; mt++)
#pragma unroll
        for (int nt = 0; nt < 4; nt++)
#pragma unroll
            for (int q = 0; q < 4; q++) c[mt][nt][q] = 0.f;

    for (int kc = 0; kc < CC; kc += 32) {
#pragma unroll
        for (int it = 0; it < 4; it++) {
            int i = tid + it * 256;
            int row = i >> 3, q = i & 7;
            float4 v = make_float4(0.f, 0.f, 0.f, 0.f);
            if (rowBase + row < M)
                v = *(const float4*)(g_o + (size_t)(rowBase + row) * CC + kc + q * 4);
            __nv_bfloat16 h0, h1, h2, h3, l0, l1, l2, l3;
            bsplit(v.x, h0, l0); bsplit(v.y, h1, l1);
            bsplit(v.z, h2, l2); bsplit(v.w, h3, l3);
            int off = row * PITCH + q * 4;
            *(uint2*)(sm + AHI + off) = make_uint2(pk(h0, h1), pk(h2, h3));
            *(uint2*)(sm + ALO + off) = make_uint2(pk(l0, l1), pk(l2, l3));
        }
#pragma unroll
        for (int it = 0; it < 2; it++) {
            int i = tid + it * 256;
            int row = i >> 2, q = i & 3;
            size_t goff = (size_t)(colBase + row) * CC + kc + q * 8;
            int off = row * PITCH + q * 8;
            *(uint4*)(sm + BHI + off) = *(const uint4*)(B1h + goff);
            *(uint4*)(sm + BLO + off) = *(const uint4*)(B1l + goff);
        }
        __syncthreads();

#pragma unroll
        for (int ks = 0; ks < 2; ks++) {
            uint32_t bh[4][2], bl[4][2];
#pragma unroll
            for (int nt = 0; nt < 4; nt++) {
                uint32_t ab = sbase + 2 * (BHI + (wn * 32 + nt * 8 + (lane & 7)) * PITCH
                                           + ks * 16 + ((lane >> 3) & 1) * 8);
                ldsm2(bh[nt], ab);
                ldsm2(bl[nt], ab + 2 * (BLO - BHI));
            }
#pragma unroll
            for (int mt = 0; mt < 4; mt++) {
                uint32_t aa = sbase + 2 * (AHI + (wm * 64 + mt * 16 + (lane & 15)) * PITCH
                                           + ks * 16 + (lane >> 4) * 8);
                uint32_t ah[4], al[4];
                ldsm4(ah, aa);
                ldsm4(al, aa + 2 * (ALO - AHI));
#pragma unroll
                for (int nt = 0; nt < 4; nt++) {
                    mma_bf16(c[mt][nt], ah, bh[nt]);
                    mma_bf16(c[mt][nt], ah, bl[nt]);
                    mma_bf16(c[mt][nt], al, bh[nt]);
                }
            }
        }
        __syncthreads();
    }

    float lsum = 0.f, lsq = 0.f;
    int mrow0 = rowBase + wm * 64;
    int col0  = colBase + wn * 32;
#pragma unroll
    for (int mt = 0; mt < 4; mt++) {
#pragma unroll
        for (int nt = 0; nt < 4; nt++) {
            int gm = mrow0 + mt * 16 + (lane >> 2);
            int gn = col0 + nt * 8 + (lane & 3) * 2;
            float b0 = b1l[gn], b1_ = b1l[gn + 1];
            if (gm < M) {
                float v0 = c[mt][nt][0] + b0;
                float v1 = c[mt][nt][1] + b1_;
                *(float2*)(g_h1 + (size_t)gm * HH + gn) = make_float2(v0, v1);
                lsum += v0 + v1;
                lsq  += v0 * v0 + v1 * v1;
            }
            if (gm + 8 < M) {
                float v2 = c[mt][nt][2] + b0;
                float v3 = c[mt][nt][3] + b1_;
                *(float2*)(g_h1 + (size_t)(gm + 8) * HH + gn) = make_float2(v2, v3);
                lsum += v2 + v3;
                lsq  += v2 * v2 + v3 * v3;
            }
        }
    }
    for (int off = 16; off; off >>= 1) {
        lsum += __shfl_down_sync(0xFFFFFFFFu, lsum, off);
        lsq  += __shfl_down_sync(0xFFFFFFFFu, lsq,  off);
    }
    if (lane == 0) { rs[wid] = lsum; rq[wid] = lsq; }
    __syncthreads();
    if (tid == 0) {
        float s = 0.f, q = 0.f;
        for (int w = 0; w < 8; w++) { s += rs[w]; q += rq[w]; }
        atomicAdd(&g_lnsum, (double)s);
        atomicAdd(&g_lnsq,  (double)q);
    }
}

// ------ GEMM2: x += relu(LN(h1)*lnw+lnb) @ W2 + b2; next-layer GN stats;
//        on the last layer also accumulates out += x_new . lin_w  --------------
__global__ __launch_bounds__(256)
void k_gemm2_mma(int M, int layer, const float* __restrict__ b2l,
                 const float* __restrict__ lnw, const float* __restrict__ lnb,
                 const float* __restrict__ linw, float* __restrict__ out, int isLast)
{
    __shared__ __align__(16) __nv_bfloat16 sm[4 * 128 * PITCH];
    const int AHI = 0, ALO = 128 * PITCH, BHI = 2 * 128 * PITCH, BLO = 3 * 128 * PITCH;

    int tid = threadIdx.x, lane = tid & 31, wid = tid >> 5;
    int wm = wid & 1, wn = wid >> 1;
    int rowBase = blockIdx.x * 128;
    const __nv_bfloat16* B2h = g_B2h + (size_t)layer * 32768;
    const __nv_bfloat16* B2l = g_B2l + (size_t)layer * 32768;
    uint32_t sbase = smem_to_u32(sm);

    double cnt = (double)M * (double)HH;
    double dm  = g_lnsum / cnt;
    double dv  = g_lnsq / cnt - dm * dm;
    float mean = (float)dm;
    float inv  = 1.f / (sqrtf(fmaxf((float)dv, 0.f)) + 1e-5f);

    float c[4][4][4];
#pragma unroll
    for (int mt = 0; mt < 4; mt++)
#pragma unroll
        for (int nt = 0; nt < 4; nt++)
#pragma unroll
            for (int q = 0; q < 4; q++) c[mt][nt][q] = 0.f;

    for (int kc = 0; kc < HH; kc += 32) {
#pragma unroll
        for (int it = 0; it < 4; it++) {
            int i = tid + it * 256;
            int row = i >> 3, q = i & 7;
            int gk = kc + q * 4;
            float4 v = make_float4(0.f, 0.f, 0.f, 0.f);
            if (rowBase + row < M)
                v = *(const float4*)(g_h1 + (size_t)(rowBase + row) * HH + gk);
            float4 w4 = *(const float4*)(lnw + gk);
            float4 b4 = *(const float4*)(lnb + gk);
            v.x = fmaxf((v.x - mean) * inv * w4.x + b4.x, 0.f);
            v.y = fmaxf((v.y - mean) * inv * w4.y + b4.y, 0.f);
            v.z = fmaxf((v.z - mean) * inv * w4.z + b4.z, 0.f);
            v.w = fmaxf((v.w - mean) * inv * w4.w + b4.w, 0.f);
            __nv_bfloat16 h0, h1, h2, h3, l0, l1, l2, l3;
            bsplit(v.x, h0, l0); bsplit(v.y, h1, l1);
            bsplit(v.z, h2, l2); bsplit(v.w, h3, l3);
            int off = row * PITCH + q * 4;
            *(uint2*)(sm + AHI + off) = make_uint2(pk(h0, h1), pk(h2, h3));
            *(uint2*)(sm + ALO + off) = make_uint2(pk(l0, l1), pk(l2, l3));
        }
#pragma unroll
        for (int it = 0; it < 2; it++) {
            int i = tid + it * 256;
            int row = i >> 2, q = i & 3;
            size_t goff = (size_t)row * HH + kc + q * 8;
            int off = row * PITCH + q * 8;
            *(uint4*)(sm + BHI + off) = *(const uint4*)(B2h + goff);
            *(uint4*)(sm + BLO + off) = *(const uint4*)(B2l + goff);
        }
        __syncthreads();

#pragma unroll
        for (int ks = 0; ks < 2; ks++) {
            uint32_t bh[4][2], bl[4][2];
#pragma unroll
            for (int nt = 0; nt < 4; nt++) {
                uint32_t ab = sbase + 2 * (BHI + (wn * 32 + nt * 8 + (lane & 7)) * PITCH
                                           + ks * 16 + ((lane >> 3) & 1) * 8);
                ldsm2(bh[nt], ab);
                ldsm2(bl[nt], ab + 2 * (BLO - BHI));
            }
#pragma unroll
            for (int mt = 0; mt < 4; mt++) {
                uint32_t aa = sbase + 2 * (AHI + (wm * 64 + mt * 16 + (lane & 15)) * PITCH
                                           + ks * 16 + (lane >> 4) * 8);
                uint32_t ah[4], al[4];
                ldsm4(ah, aa);
                ldsm4(al, aa + 2 * (ALO - AHI));
#pragma unroll
                for (int nt = 0; nt < 4; nt++) {
                    mma_bf16(c[mt][nt], ah, bh[nt]);
                    mma_bf16(c[mt][nt], ah, bl[nt]);
                    mma_bf16(c[mt][nt], al, bh[nt]);
                }
            }
        }
        __syncthreads();
    }

    // epilogue: residual add into g_x + next-layer GN stats (+ final dot on last)
    int mrow0 = rowBase + wm * 64;
    int col0  = wn * 32;
    float fin0[4] = {0.f, 0.f, 0.f, 0.f};
    float fin1[4] = {0.f, 0.f, 0.f, 0.f};
#pragma unroll
    for (int nt = 0; nt < 4; nt++) {
        int gn = col0 + nt * 8 + (lane & 3) * 2;
        float b0 = b2l[gn], b1_ = b2l[gn + 1];
        float lw0 = 0.f, lw1 = 0.f;
        if (isLast) { lw0 = __ldg(linw + gn); lw1 = __ldg(linw + gn + 1); }
        float cs0 = 0.f, cs1 = 0.f, cq0 = 0.f, cq1 = 0.f;
#pragma unroll
        for (int mt = 0; mt < 4; mt++) {
            int gm = mrow0 + mt * 16 + (lane >> 2);
            if (gm < M) {
                float2 old = *(float2*)(g_x + (size_t)gm * CC + gn);
                float nx0 = old.x + c[mt][nt][0] + b0;
                float nx1 = old.y + c[mt][nt][1] + b1_;
                *(float2*)(g_x + (size_t)gm * CC + gn) = make_float2(nx0, nx1);
                cs0 += nx0; cs1 += nx1;
                cq0 += nx0 * nx0; cq1 += nx1 * nx1;
                fin0[mt] += nx0 * lw0 + nx1 * lw1;
            }
            if (gm + 8 < M) {
                float2 old = *(float2*)(g_x + (size_t)(gm + 8) * CC + gn);
                float nx2 = old.x + c[mt][nt][2] + b0;
                float nx3 = old.y + c[mt][nt][3] + b1_;
                *(float2*)(g_x + (size_t)(gm + 8) * CC + gn) = make_float2(nx2, nx3);
                cs0 += nx2; cs1 += nx3;
                cq0 += nx2 * nx2; cq1 += nx3 * nx3;
                fin1[mt] += nx2 * lw0 + nx3 * lw1;
            }
        }
        if (!isLast) {
#pragma unroll
            for (int off = 16; off >= 4; off >>= 1) {
                cs0 += __shfl_down_sync(0xFFFFFFFFu, cs0, off);
                cs1 += __shfl_down_sync(0xFFFFFFFFu, cs1, off);
                cq0 += __shfl_down_sync(0xFFFFFFFFu, cq0, off);
                cq1 += __shfl_down_sync(0xFFFFFFFFu, cq1, off);
            }
            if (lane < 4) {
                atomicAdd(&g_gnsum[gn],     cs0);
                atomicAdd(&g_gnsum[gn + 1], cs1);
                atomicAdd(&g_gnsq[gn],      cq0);
                atomicAdd(&g_gnsq[gn + 1],  cq1);
            }
        }
    }
    if (isLast) {
#pragma unroll
        for (int mt = 0; mt < 4; mt++) {
            float p0 = fin0[mt], p1 = fin1[mt];
            p0 += __shfl_xor_sync(0xFFFFFFFFu, p0, 1);
            p0 += __shfl_xor_sync(0xFFFFFFFFu, p0, 2);
            p1 += __shfl_xor_sync(0xFFFFFFFFu, p1, 1);
            p1 += __shfl_xor_sync(0xFFFFFFFFu, p1, 2);
            if ((lane & 3) == 0) {
                int gm = mrow0 + mt * 16 + (lane >> 2);
                if (gm < M)     atomicAdd(out + gm,     p0);
                if (gm + 8 < M) atomicAdd(out + gm + 8, p1);
            }
        }
    }
}

// ---------------- launch ------------------------------------------------------
extern "C" void kernel_launch(void* const* d_in, const int* in_sizes, int n_in,
                              void* d_out, int out_size)
{
    const float* x    = (const float*)d_in[0];
    const int*   src  = (const int*)  d_in[1];
    const int*   dst  = (const int*)  d_in[2];
    const float* W1   = (const float*)d_in[3];
    const float* b1   = (const float*)d_in[4];
    const float* lnw  = (const float*)d_in[5];
    const float* lnb  = (const float*)d_in[6];
    const float* W2   = (const float*)d_in[7];
    const float* b2   = (const float*)d_in[8];
    const float* t    = (const float*)d_in[9];
    const float* gnw  = (const float*)d_in[10];
    const float* gnb  = (const float*)d_in[11];
    const float* gna  = (const float*)d_in[12];
    const float* linw = (const float*)d_in[13];
    const float* linb = (const float*)d_in[14];
    float* out = (float*)d_out;

    int n = in_sizes[0] / CC;   // 50000
    int E = in_sizes[1];        // 600000

    k_init<<<(n + 255) / 256, 256>>>(n, out, linb);
    k_setup<<<2048, 256>>>(x, n, W1, W2, dst, E);

    int nb = (n + 1023) / 1024;
    k_scan1<<<nb, 1024>>>(n);
    k_scan2<<<1, 64>>>(nb, n, E);
    k_scan3<<<(n + 255) / 256, 256>>>(n);
    k_fill<<<1024, 256>>>(src, dst, E);

    int mBlocks = (n + 127) / 128;
    for (int l = 0; l < LL; l++) {
        k_gn<<<512, 128>>>(n, gnw + l * CC, gnb + l * CC, gna + l * CC);
        k_edge<<<(n + 7) / 8, 256>>>(n, gnw + l * CC, gnb + l * CC, gna + l * CC, t + l);
        dim3 g1(mBlocks, 2);
        k_gemm1_mma<<<g1, 256>>>(n, l, b1 + l * HH);
        k_gemm2_mma<<<mBlocks, 256>>>(n, l, b2 + l * CC, lnw + l * HH, lnb + l * HH,
                                      linw, out, (l == LL - 1) ? 1 : 0);
    }
    (void)n_in; (void)out_size;
}

// round 17
// speedup vs baseline: 1.2234x; 1.2234x over previous
#include <cuda_runtime.h>
#include <cuda_bf16.h>
#include <cuda_fp16.h>
#include <cstdint>

#define CC 128
#define HH 256
#define LL 4
#define NMAX 50176
#define EMAX 602112

// ---------------- scratch (device globals; no allocation allowed) ------------
__device__ float  g_x [NMAX * CC];
__device__ float  g_o [NMAX * CC];
__device__ __half g_h1h[NMAX * HH];   // fp16 MLP hidden (pre-LN)
__device__ int    g_rowptr[NMAX + 1];
__device__ int    g_cursor[NMAX];
__device__ int    g_col[EMAX];
__device__ int    g_part[64];
__device__ float  g_gnsum[CC];
__device__ float  g_gnsq [CC];
__device__ double g_lnsum;
__device__ double g_lnsq;
// bf16 hi/lo weight images, [n][k] row-major, per layer (32768 elems each)
__device__ __align__(16) __nv_bfloat16 g_B1h[LL * 32768];
__device__ __align__(16) __nv_bfloat16 g_B1l[LL * 32768];
__device__ __align__(16) __nv_bfloat16 g_B2h[LL * 32768];
__device__ __align__(16) __nv_bfloat16 g_B2l[LL * 32768];

// ---------------- mma.sync helpers (legal on plain sm_100) -------------------
__device__ __forceinline__ uint32_t smem_to_u32(const void* p) {
    uint32_t a;
    asm("{ .reg .u64 t; cvta.to.shared.u64 t, %1; cvt.u32.u64 %0, t; }" : "=r"(a) : "l"(p));
    return a;
}
__device__ __forceinline__ void ldsm4(uint32_t* r, uint32_t a) {
    asm volatile("ldmatrix.sync.aligned.m8n8.x4.shared.b16 {%0,%1,%2,%3}, [%4];"
                 : "=r"(r[0]), "=r"(r[1]), "=r"(r[2]), "=r"(r[3]) : "r"(a));
}
__device__ __forceinline__ void ldsm2(uint32_t* r, uint32_t a) {
    asm volatile("ldmatrix.sync.aligned.m8n8.x2.shared.b16 {%0,%1}, [%2];"
                 : "=r"(r[0]), "=r"(r[1]) : "r"(a));
}
__device__ __forceinline__ void mma_bf16(float* c, const uint32_t* a, const uint32_t* b) {
    asm volatile(
        "mma.sync.aligned.m16n8k16.row.col.f32.bf16.bf16.f32 "
        "{%0,%1,%2,%3}, {%4,%5,%6,%7}, {%8,%9}, {%0,%1,%2,%3};"
        : "+f"(c[0]), "+f"(c[1]), "+f"(c[2]), "+f"(c[3])
        : "r"(a[0]), "r"(a[1]), "r"(a[2]), "r"(a[3]), "r"(b[0]), "r"(b[1]));
}
__device__ __forceinline__ void bsplit(float v, __nv_bfloat16& h, __nv_bfloat16& l) {
    h = __float2bfloat16(v);
    l = __float2bfloat16(v - __bfloat162float(h));
}
__device__ __forceinline__ uint32_t pk(__nv_bfloat16 a, __nv_bfloat16 b) {
    __nv_bfloat162 t; t.x = a; t.y = b;
    return *reinterpret_cast<uint32_t*>(&t);
}

// smem tile pitch: 40 bf16 (80 B) -> ldmatrix rows hit distinct bank groups
#define PITCH 40

// ---------------- init: cursor zero + stats zero + out = lin_b ---------------
__global__ void k_init(int n, float* __restrict__ out, const float* __restrict__ linb)
{
    int i = blockIdx.x * blockDim.x + threadIdx.x;
    if (i < n) {
        g_cursor[i] = 0;
        out[i] = __ldg(linb);
    }
    if (blockIdx.x == 0) {
        if (threadIdx.x < 128) { g_gnsum[threadIdx.x] = 0.f; g_gnsq[threadIdx.x] = 0.f; }
        if (threadIdx.x == 128) g_lnsum = 0.0;
        if (threadIdx.x == 129) g_lnsq  = 0.0;
    }
}

// ---- mega setup: copyin+gn-stats (blocks 0..511) | wconv (512..1535) | count (1536..2047)
__global__ void k_setup(const float* __restrict__ x, int n,
                        const float* __restrict__ W1, const float* __restrict__ W2,
                        const int* __restrict__ dst, int E)
{
    int b = blockIdx.x;
    int tid = threadIdx.x;
    if (b < 512) {
        int c = tid & 127, sub = tid >> 7;
        float s = 0.f, q = 0.f;
        for (int row = b * 2 + sub; row < n; row += 1024) {
            float v = x[(size_t)row * CC + c];
            g_x[(size_t)row * CC + c] = v;
            s += v;
            q += v * v;
        }
        atomicAdd(&g_gnsum[c], s);
        atomicAdd(&g_gnsq[c],  q);
    } else if (b < 1536) {
        int i = (b - 512) * 256 + tid;
        int l = i >> 16;
        int r = i & 65535;
        __nv_bfloat16 h, lo;
        if (r < 32768) {                 // B1[n][k] = W1[l][k][n]
            int nn = r >> 7, k = r & 127;
            float v = W1[((size_t)l * CC + k) * HH + nn];
            bsplit(v, h, lo);
            g_B1h[l * 32768 + nn * 128 + k] = h;
            g_B1l[l * 32768 + nn * 128 + k] = lo;
        } else {                          // B2[n][k] = W2[l][k][n]
            r -= 32768;
            int nn = r >> 8, k = r & 255;
            float v = W2[((size_t)l * HH + k) * CC + nn];
            bsplit(v, h, lo);
            g_B2h[l * 32768 + nn * 256 + k] = h;
            g_B2l[l * 32768 + nn * 256 + k] = lo;
        }
    } else {
        int i = (b - 1536) * 256 + tid;
        for (; i < E; i += 512 * 256) atomicAdd(&g_cursor[dst[i]], 1);
    }
}

// ---------------- CSR scan + fill ---------------------------------------------
__global__ void k_scan1(int n)
{
    __shared__ int sh[1024];
    int i = blockIdx.x * 1024 + threadIdx.x;
    int v = (i < n) ? g_cursor[i] : 0;
    sh[threadIdx.x] = v;
    __syncthreads();
    for (int off = 1; off < 1024; off <<= 1) {
        int tv = (threadIdx.x >= off) ? sh[threadIdx.x - off] : 0;
        __syncthreads();
        sh[threadIdx.x] += tv;
        __syncthreads();
    }
    if (i < n) g_rowptr[i] = sh[threadIdx.x] - v;
    if (threadIdx.x == 1023) g_part[blockIdx.x] = sh[1023];
}

__global__ void k_scan2(int nb, int n, int E)
{
    int tid = threadIdx.x;  // 64 threads
    int v = (tid < nb) ? g_part[tid] : 0;
    int x = v;
    for (int off = 1; off < 32; off <<= 1) {
        int y = __shfl_up_sync(0xFFFFFFFFu, x, off);
        if ((tid & 31) >= off) x += y;
    }
    __shared__ int c0;
    if (tid == 31) c0 = x;
    __syncthreads();
    if (tid >= 32) x += c0;
    if (tid < nb) g_part[tid] = x - v;
    if (tid == 0) g_rowptr[n] = E;
}

__global__ void k_scan3(int n)
{
    int i = blockIdx.x * blockDim.x + threadIdx.x;
    if (i < n) {
        int val = g_rowptr[i] + g_part[i >> 10];
        g_rowptr[i] = val;
        g_cursor[i] = val;
    }
}

__global__ void k_fill(const int* __restrict__ src, const int* __restrict__ dst, int E)
{
    int i = blockIdx.x * blockDim.x + threadIdx.x;
    int stride = gridDim.x * blockDim.x;
    for (; i < E; i += stride) {
        int p = atomicAdd(&g_cursor[dst[i]], 1);
        g_col[p] = src[i];
    }
}

// ---- GENConv softmax aggregation with GraphNorm+ReLU applied inline ---------
// fp32 gather (latency-bound; fp16 operand measured slower). 4-edge unroll.
__global__ void k_edge(int n, const float* __restrict__ gnw,
                       const float* __restrict__ gnb, const float* __restrict__ gna,
                       const float* __restrict__ t_ptr)
{
    if (blockIdx.x == 0) {
        if (threadIdx.x == 0) g_lnsum = 0.0;
        if (threadIdx.x == 1) g_lnsq  = 0.0;
    }
    int warp = (blockIdx.x * blockDim.x + threadIdx.x) >> 5;
    if (warp >= n) return;
    int lane = threadIdx.x & 31;
    int co = lane * 4;

    float invn = 1.f / (float)n;
    float4 s4 = *(const float4*)(g_gnsum + co);
    float4 q4 = *(const float4*)(g_gnsq  + co);
    float4 a4 = __ldg((const float4*)(gna + co));
    float4 w4 = __ldg((const float4*)(gnw + co));
    float4 b4 = __ldg((const float4*)(gnb + co));
    float mX = s4.x * invn, mY = s4.y * invn, mZ = s4.z * invn, mW = s4.w * invn;
    float wvX = w4.x * rsqrtf(q4.x * invn - (2.f * a4.x - a4.x * a4.x) * mX * mX + 1e-5f);
    float wvY = w4.y * rsqrtf(q4.y * invn - (2.f * a4.y - a4.y * a4.y) * mY * mY + 1e-5f);
    float wvZ = w4.z * rsqrtf(q4.z * invn - (2.f * a4.z - a4.z * a4.z) * mZ * mZ + 1e-5f);
    float wvW = w4.w * rsqrtf(q4.w * invn - (2.f * a4.w - a4.w * a4.w) * mW * mW + 1e-5f);
    float amX = a4.x * mX, amY = a4.y * mY, amZ = a4.z * mZ, amW = a4.w * mW;
    float t = __ldg(t_ptr);

    int beg = g_rowptr[warp], end = g_rowptr[warp + 1];

    float4 s1a = make_float4(0.f, 0.f, 0.f, 0.f);
    float4 s2a = make_float4(0.f, 0.f, 0.f, 0.f);
    float4 s1b = make_float4(0.f, 0.f, 0.f, 0.f);
    float4 s2b = make_float4(0.f, 0.f, 0.f, 0.f);

#define GNRELU(v, rx, ry, rz, rw) \
    float rx = fmaxf(wvX * ((v).x - amX) + b4.x, 0.f) + 1e-7f; \
    float ry = fmaxf(wvY * ((v).y - amY) + b4.y, 0.f) + 1e-7f; \
    float rz = fmaxf(wvZ * ((v).z - amZ) + b4.z, 0.f) + 1e-7f; \
    float rw = fmaxf(wvW * ((v).w - amW) + b4.w, 0.f) + 1e-7f;
#define ACCUM(S1, S2, rx, ry, rz, rw) { \
    float ex = __expf(t * rx), ey = __expf(t * ry); \
    float ez = __expf(t * rz), ew = __expf(t * rw); \
    S1.x += ex; S1.y += ey; S1.z += ez; S1.w += ew; \
    S2.x += rx * ex; S2.y += ry * ey; S2.z += rz * ez; S2.w += rw * ew; }

    int e = beg;
    for (; e + 4 <= end; e += 4) {
        int i0 = g_col[e],     i1 = g_col[e + 1];
        int i2 = g_col[e + 2], i3 = g_col[e + 3];
        float4 v0 = __ldg((const float4*)(g_x + (size_t)i0 * CC + co));
        float4 v1 = __ldg((const float4*)(g_x + (size_t)i1 * CC + co));
        float4 v2 = __ldg((const float4*)(g_x + (size_t)i2 * CC + co));
        float4 v3 = __ldg((const float4*)(g_x + (size_t)i3 * CC + co));
        { GNRELU(v0, x0, y0, z0, w0) ACCUM(s1a, s2a, x0, y0, z0, w0) }
        { GNRELU(v1, x1, y1, z1, w1) ACCUM(s1b, s2b, x1, y1, z1, w1) }
        { GNRELU(v2, x2, y2, z2, w2) ACCUM(s1a, s2a, x2, y2, z2, w2) }
        { GNRELU(v3, x3, y3, z3, w3) ACCUM(s1b, s2b, x3, y3, z3, w3) }
    }
    for (; e < end; e++) {
        int i0 = g_col[e];
        float4 v0 = __ldg((const float4*)(g_x + (size_t)i0 * CC + co));
        { GNRELU(v0, x0, y0, z0, w0) ACCUM(s1a, s2a, x0, y0, z0, w0) }
    }
    s1a.x += s1b.x; s1a.y += s1b.y; s1a.z += s1b.z; s1a.w += s1b.w;
    s2a.x += s2b.x; s2a.y += s2b.y; s2a.z += s2b.z; s2a.w += s2b.w;

    float4 hx = *(const float4*)(g_x + (size_t)warp * CC + co);
    float hX = fmaxf(wvX * (hx.x - amX) + b4.x, 0.f);
    float hY = fmaxf(wvY * (hx.y - amY) + b4.y, 0.f);
    float hZ = fmaxf(wvZ * (hx.z - amZ) + b4.z, 0.f);
    float hW = fmaxf(wvW * (hx.w - amW) + b4.w, 0.f);
    float4 o;
    o.x = s2a.x / (s1a.x + 1e-16f) + hX;
    o.y = s2a.y / (s1a.y + 1e-16f) + hY;
    o.z = s2a.z / (s1a.z + 1e-16f) + hZ;
    o.w = s2a.w / (s1a.w + 1e-16f) + hW;
    *(float4*)(g_o + (size_t)warp * CC + co) = o;
}

// ---------------- GEMM1: h1 = o @ W1 + b1 (h1 stored fp16) + LN stats --------
__global__ __launch_bounds__(256)
void k_gemm1_mma(int M, int layer, const float* __restrict__ b1l)
{
    __shared__ __align__(16) __nv_bfloat16 sm[4 * 128 * PITCH];
    __shared__ float rs[8], rq[8];
    const int AHI = 0, ALO = 128 * PITCH, BHI = 2 * 128 * PITCH, BLO = 3 * 128 * PITCH;

    int tid = threadIdx.x, lane = tid & 31, wid = tid >> 5;
    if (blockIdx.x == 0 && blockIdx.y == 0 && tid < 128) {
        g_gnsum[tid] = 0.f;
        g_gnsq[tid]  = 0.f;
    }
    int wm = wid & 1, wn = wid >> 1;
    int rowBase = blockIdx.x * 128;
    int colBase = blockIdx.y * 128;
    const __nv_bfloat16* B1h = g_B1h + (size_t)layer * 32768;
    const __nv_bfloat16* B1l = g_B1l + (size_t)layer * 32768;
    uint32_t sbase = smem_to_u32(sm);

    float c[4][4][4];
#pragma unroll
    for (int mt = 0; mt < 4; mt++)
#pragma unroll
        for (int nt = 0; nt < 4; nt++)
#pragma unroll
            for (int q = 0; q < 4; q++) c[mt][nt][q] = 0.f;

    for (int kc = 0; kc < CC; kc += 32) {
#pragma unroll
        for (int it = 0; it < 4; it++) {
            int i = tid + it * 256;
            int row = i >> 3, q = i & 7;
            float4 v = make_float4(0.f, 0.f, 0.f, 0.f);
            if (rowBase + row < M)
                v = *(const float4*)(g_o + (size_t)(rowBase + row) * CC + kc + q * 4);
            __nv_bfloat16 h0, h1, h2, h3, l0, l1, l2, l3;
            bsplit(v.x, h0, l0); bsplit(v.y, h1, l1);
            bsplit(v.z, h2, l2); bsplit(v.w, h3, l3);
            int off = row * PITCH + q * 4;
            *(uint2*)(sm + AHI + off) = make_uint2(pk(h0, h1), pk(h2, h3));
            *(uint2*)(sm + ALO + off) = make_uint2(pk(l0, l1), pk(l2, l3));
        }
#pragma unroll
        for (int it = 0; it < 2; it++) {
            int i = tid + it * 256;
            int row = i >> 2, q = i & 3;
            size_t goff = (size_t)(colBase + row) * CC + kc + q * 8;
            int off = row * PITCH + q * 8;
            *(uint4*)(sm + BHI + off) = *(const uint4*)(B1h + goff);
            *(uint4*)(sm + BLO + off) = *(const uint4*)(B1l + goff);
        }
        __syncthreads();

#pragma unroll
        for (int ks = 0; ks < 2; ks++) {
            uint32_t bh[4][2], bl[4][2];
#pragma unroll
            for (int nt = 0; nt < 4; nt++) {
                uint32_t ab = sbase + 2 * (BHI + (wn * 32 + nt * 8 + (lane & 7)) * PITCH
                                           + ks * 16 + ((lane >> 3) & 1) * 8);
                ldsm2(bh[nt], ab);
                ldsm2(bl[nt], ab + 2 * (BLO - BHI));
            }
#pragma unroll
            for (int mt = 0; mt < 4; mt++) {
                uint32_t aa = sbase + 2 * (AHI + (wm * 64 + mt * 16 + (lane & 15)) * PITCH
                                           + ks * 16 + (lane >> 4) * 8);
                uint32_t ah[4], al[4];
                ldsm4(ah, aa);
                ldsm4(al, aa + 2 * (ALO - AHI));
#pragma unroll
                for (int nt = 0; nt < 4; nt++) {
                    mma_bf16(c[mt][nt], ah, bh[nt]);
                    mma_bf16(c[mt][nt], ah, bl[nt]);
                    mma_bf16(c[mt][nt], al, bh[nt]);
                }
            }
        }
        __syncthreads();
    }

    float lsum = 0.f, lsq = 0.f;
    int mrow0 = rowBase + wm * 64;
    int col0  = colBase + wn * 32;
#pragma unroll
    for (int mt = 0; mt < 4; mt++) {
#pragma unroll
        for (int nt = 0; nt < 4; nt++) {
            int gm = mrow0 + mt * 16 + (lane >> 2);
            int gn = col0 + nt * 8 + (lane & 3) * 2;
            float b0 = b1l[gn], b1_ = b1l[gn + 1];
            if (gm < M) {
                float v0 = c[mt][nt][0] + b0;
                float v1 = c[mt][nt][1] + b1_;
                *(__half2*)(g_h1h + (size_t)gm * HH + gn) = __floats2half2_rn(v0, v1);
                lsum += v0 + v1;
                lsq  += v0 * v0 + v1 * v1;
            }
            if (gm + 8 < M) {
                float v2 = c[mt][nt][2] + b0;
                float v3 = c[mt][nt][3] + b1_;
                *(__half2*)(g_h1h + (size_t)(gm + 8) * HH + gn) = __floats2half2_rn(v2, v3);
                lsum += v2 + v3;
                lsq  += v2 * v2 + v3 * v3;
            }
        }
    }
    for (int off = 16; off; off >>= 1) {
        lsum += __shfl_down_sync(0xFFFFFFFFu, lsum, off);
        lsq  += __shfl_down_sync(0xFFFFFFFFu, lsq,  off);
    }
    if (lane == 0) { rs[wid] = lsum; rq[wid] = lsq; }
    __syncthreads();
    if (tid == 0) {
        float s = 0.f, q = 0.f;
        for (int w = 0; w < 8; w++) { s += rs[w]; q += rq[w]; }
        atomicAdd(&g_lnsum, (double)s);
        atomicAdd(&g_lnsq,  (double)q);
    }
}

// ------ GEMM2: x += relu(LN(h1)*lnw+lnb) @ W2 + b2 (h1 read fp16);
//        next-layer GN stats; last layer also out += x_new . lin_w ------------
__global__ __launch_bounds__(256)
void k_gemm2_mma(int M, int layer, const float* __restrict__ b2l,
                 const float* __restrict__ lnw, const float* __restrict__ lnb,
                 const float* __restrict__ linw, float* __restrict__ out, int isLast)
{
    __shared__ __align__(16) __nv_bfloat16 sm[4 * 128 * PITCH];
    const int AHI = 0, ALO = 128 * PITCH, BHI = 2 * 128 * PITCH, BLO = 3 * 128 * PITCH;

    int tid = threadIdx.x, lane = tid & 31, wid = tid >> 5;
    int wm = wid & 1, wn = wid >> 1;
    int rowBase = blockIdx.x * 128;
    const __nv_bfloat16* B2h = g_B2h + (size_t)layer * 32768;
    const __nv_bfloat16* B2l = g_B2l + (size_t)layer * 32768;
    uint32_t sbase = smem_to_u32(sm);

    double cnt = (double)M * (double)HH;
    double dm  = g_lnsum / cnt;
    double dv  = g_lnsq / cnt - dm * dm;
    float mean = (float)dm;
    float inv  = 1.f / (sqrtf(fmaxf((float)dv, 0.f)) + 1e-5f);

    float c[4][4][4];
#pragma unroll
    for (int mt = 0; mt < 4; mt++)
#pragma unroll
        for (int nt = 0; nt < 4; nt++)
#pragma unroll
            for (int q = 0; q < 4; q++) c[mt][nt][q] = 0.f;

    for (int kc = 0; kc < HH; kc += 32) {
#pragma unroll
        for (int it = 0; it < 4; it++) {
            int i = tid + it * 256;
            int row = i >> 3, q = i & 7;
            int gk = kc + q * 4;
            float4 v = make_float4(0.f, 0.f, 0.f, 0.f);
            if (rowBase + row < M) {
                uint2 u = *(const uint2*)(g_h1h + (size_t)(rowBase + row) * HH + gk);
                float2 f0 = __half22float2(*reinterpret_cast<const __half2*>(&u.x));
                float2 f1 = __half22float2(*reinterpret_cast<const __half2*>(&u.y));
                v = make_float4(f0.x, f0.y, f1.x, f1.y);
            }
            float4 w4 = *(const float4*)(lnw + gk);
            float4 b4 = *(const float4*)(lnb + gk);
            v.x = fmaxf((v.x - mean) * inv * w4.x + b4.x, 0.f);
            v.y = fmaxf((v.y - mean) * inv * w4.y + b4.y, 0.f);
            v.z = fmaxf((v.z - mean) * inv * w4.z + b4.z, 0.f);
            v.w = fmaxf((v.w - mean) * inv * w4.w + b4.w, 0.f);
            __nv_bfloat16 h0, h1, h2, h3, l0, l1, l2, l3;
            bsplit(v.x, h0, l0); bsplit(v.y, h1, l1);
            bsplit(v.z, h2, l2); bsplit(v.w, h3, l3);
            int off = row * PITCH + q * 4;
            *(uint2*)(sm + AHI + off) = make_uint2(pk(h0, h1), pk(h2, h3));
            *(uint2*)(sm + ALO + off) = make_uint2(pk(l0, l1), pk(l2, l3));
        }
#pragma unroll
        for (int it = 0; it < 2; it++) {
            int i = tid + it * 256;
            int row = i >> 2, q = i & 3;
            size_t goff = (size_t)row * HH + kc + q * 8;
            int off = row * PITCH + q * 8;
            *(uint4*)(sm + BHI + off) = *(const uint4*)(B2h + goff);
            *(uint4*)(sm + BLO + off) = *(const uint4*)(B2l + goff);
        }
        __syncthreads();

#pragma unroll
        for (int ks = 0; ks < 2; ks++) {
            uint32_t bh[4][2], bl[4][2];
#pragma unroll
            for (int nt = 0; nt < 4; nt++) {
                uint32_t ab = sbase + 2 * (BHI + (wn * 32 + nt * 8 + (lane & 7)) * PITCH
                                           + ks * 16 + ((lane >> 3) & 1) * 8);
                ldsm2(bh[nt], ab);
                ldsm2(bl[nt], ab + 2 * (BLO - BHI));
            }
#pragma unroll
            for (int mt = 0; mt < 4; mt++) {
                uint32_t aa = sbase + 2 * (AHI + (wm * 64 + mt * 16 + (lane & 15)) * PITCH
                                           + ks * 16 + (lane >> 4) * 8);
                uint32_t ah[4], al[4];
                ldsm4(ah, aa);
                ldsm4(al, aa + 2 * (ALO - AHI));
#pragma unroll
                for (int nt = 0; nt < 4; nt++) {
                    mma_bf16(c[mt][nt], ah, bh[nt]);
                    mma_bf16(c[mt][nt], ah, bl[nt]);
                    mma_bf16(c[mt][nt], al, bh[nt]);
                }
            }
        }
        __syncthreads();
    }

    // epilogue: residual add into g_x + next-layer GN stats (+ final dot on last)
    int mrow0 = rowBase + wm * 64;
    int col0  = wn * 32;
    float fin0[4] = {0.f, 0.f, 0.f, 0.f};
    float fin1[4] = {0.f, 0.f, 0.f, 0.f};
#pragma unroll
    for (int nt = 0; nt < 4; nt++) {
        int gn = col0 + nt * 8 + (lane & 3) * 2;
        float b0 = b2l[gn], b1_ = b2l[gn + 1];
        float lw0 = 0.f, lw1 = 0.f;
        if (isLast) { lw0 = __ldg(linw + gn); lw1 = __ldg(linw + gn + 1); }
        float cs0 = 0.f, cs1 = 0.f, cq0 = 0.f, cq1 = 0.f;
#pragma unroll
        for (int mt = 0; mt < 4; mt++) {
            int gm = mrow0 + mt * 16 + (lane >> 2);
            if (gm < M) {
                float2 old = *(float2*)(g_x + (size_t)gm * CC + gn);
                float nx0 = old.x + c[mt][nt][0] + b0;
                float nx1 = old.y + c[mt][nt][1] + b1_;
                *(float2*)(g_x + (size_t)gm * CC + gn) = make_float2(nx0, nx1);
                cs0 += nx0; cs1 += nx1;
                cq0 += nx0 * nx0; cq1 += nx1 * nx1;
                fin0[mt] += nx0 * lw0 + nx1 * lw1;
            }
            if (gm + 8 < M) {
                float2 old = *(float2*)(g_x + (size_t)(gm + 8) * CC + gn);
                float nx2 = old.x + c[mt][nt][2] + b0;
                float nx3 = old.y + c[mt][nt][3] + b1_;
                *(float2*)(g_x + (size_t)(gm + 8) * CC + gn) = make_float2(nx2, nx3);
                cs0 += nx2; cs1 += nx3;
                cq0 += nx2 * nx2; cq1 += nx3 * nx3;
                fin1[mt] += nx2 * lw0 + nx3 * lw1;
            }
        }
        if (!isLast) {
#pragma unroll
            for (int off = 16; off >= 4; off >>= 1) {
                cs0 += __shfl_down_sync(0xFFFFFFFFu, cs0, off);
                cs1 += __shfl_down_sync(0xFFFFFFFFu, cs1, off);
                cq0 += __shfl_down_sync(0xFFFFFFFFu, cq0, off);
                cq1 += __shfl_down_sync(0xFFFFFFFFu, cq1, off);
            }
            if (lane < 4) {
                atomicAdd(&g_gnsum[gn],     cs0);
                atomicAdd(&g_gnsum[gn + 1], cs1);
                atomicAdd(&g_gnsq[gn],      cq0);
                atomicAdd(&g_gnsq[gn + 1],  cq1);
            }
        }
    }
    if (isLast) {
#pragma unroll
        for (int mt = 0; mt < 4; mt++) {
            float p0 = fin0[mt], p1 = fin1[mt];
            p0 += __shfl_xor_sync(0xFFFFFFFFu, p0, 1);
            p0 += __shfl_xor_sync(0xFFFFFFFFu, p0, 2);
            p1 += __shfl_xor_sync(0xFFFFFFFFu, p1, 1);
            p1 += __shfl_xor_sync(0xFFFFFFFFu, p1, 2);
            if ((lane & 3) == 0) {
                int gm = mrow0 + mt * 16 + (lane >> 2);
                if (gm < M)     atomicAdd(out + gm,     p0);
                if (gm + 8 < M) atomicAdd(out + gm + 8, p1);
            }
        }
    }
}

// ---------------- launch ------------------------------------------------------
extern "C" void kernel_launch(void* const* d_in, const int* in_sizes, int n_in,
                              void* d_out, int out_size)
{
    const float* x    = (const float*)d_in[0];
    const int*   src  = (const int*)  d_in[1];
    const int*   dst  = (const int*)  d_in[2];
    const float* W1   = (const float*)d_in[3];
    const float* b1   = (const float*)d_in[4];
    const float* lnw  = (const float*)d_in[5];
    const float* lnb  = (const float*)d_in[6];
    const float* W2   = (const float*)d_in[7];
    const float* b2   = (const float*)d_in[8];
    const float* t    = (const float*)d_in[9];
    const float* gnw  = (const float*)d_in[10];
    const float* gnb  = (const float*)d_in[11];
    const float* gna  = (const float*)d_in[12];
    const float* linw = (const float*)d_in[13];
    const float* linb = (const float*)d_in[14];
    float* out = (float*)d_out;

    int n = in_sizes[0] / CC;   // 50000
    int E = in_sizes[1];        // 600000

    k_init<<<(n + 255) / 256, 256>>>(n, out, linb);
    k_setup<<<2048, 256>>>(x, n, W1, W2, dst, E);

    int nb = (n + 1023) / 1024;
    k_scan1<<<nb, 1024>>>(n);
    k_scan2<<<1, 64>>>(nb, n, E);
    k_scan3<<<(n + 255) / 256, 256>>>(n);
    k_fill<<<1024, 256>>>(src, dst, E);

    int mBlocks = (n + 127) / 128;
    for (int l = 0; l < LL; l++) {
        k_edge<<<(n + 7) / 8, 256>>>(n, gnw + l * CC, gnb + l * CC, gna + l * CC, t + l);
        dim3 g1(mBlocks, 2);
        k_gemm1_mma<<<g1, 256>>>(n, l, b1 + l * HH);
        k_gemm2_mma<<<mBlocks, 256>>>(n, l, b2 + l * CC, lnw + l * HH, lnb + l * HH,
                                      linw, out, (l == LL - 1) ? 1 : 0);
    }
    (void)n_in; (void)out_size;
}